// round 1
// baseline (speedup 1.0000x reference)
#include <cuda_runtime.h>
#include <math.h>

#define HEADS   4
#define HD      32
#define NTOK    256      // tokens per window (16x16)
#define NWIN    512      // 2 * 16 * 16 windows
#define POSN    961      // (2*16-1)^2
#define QKSCALE 0.17677669529663689f  // 32^-0.5

// ---------------- scratch (device globals; no allocation allowed) ----------------
__device__ float g_q[NWIN * HEADS * NTOK * HD];   // 64MB, window-partitioned [w][h][n][d]
__device__ float g_k[NWIN * HEADS * NTOK * HD];
__device__ float g_v[NWIN * HEADS * NTOK * HD];
__device__ float g_wT[128 * 384];                 // g_wT[k][j] = qkv_w[j][k] * norm1_g[k]
__device__ float g_cs[384];                       // sum_k g_wT[k][j]
__device__ float g_cb[384];                       // sum_k norm1_b[k]*qkv_w[j][k] + qkv_b[j]
__device__ float g_pos[HEADS * POSN];             // head-major pos bias table

// ---------------- pos-bias MLP ----------------
__device__ __forceinline__ void ln_relu8(float* a, const float* g, const float* b) {
    float m = 0.f;
#pragma unroll
    for (int u = 0; u < 8; u++) m += a[u];
    m *= 0.125f;
    float v = 0.f;
#pragma unroll
    for (int u = 0; u < 8; u++) { float d = a[u] - m; v += d * d; }
    v *= 0.125f;
    float r = rsqrtf(v + 1e-5f);
#pragma unroll
    for (int u = 0; u < 8; u++) a[u] = fmaxf((a[u] - m) * r * g[u] + b[u], 0.f);
}

__device__ __forceinline__ void fc8(const float* a, float* y, const float* w, const float* b) {
#pragma unroll
    for (int o = 0; o < 8; o++) {
        float s = b[o];
#pragma unroll
        for (int u = 0; u < 8; u++) s += a[u] * w[o * 8 + u];
        y[o] = s;
    }
}

__global__ void prep_pos_kernel(
    const float* __restrict__ pp_w, const float* __restrict__ pp_b,
    const float* __restrict__ l1_g, const float* __restrict__ l1_b,
    const float* __restrict__ f1_w, const float* __restrict__ f1_b,
    const float* __restrict__ l2_g, const float* __restrict__ l2_b,
    const float* __restrict__ f2_w, const float* __restrict__ f2_b,
    const float* __restrict__ l3_g, const float* __restrict__ l3_b,
    const float* __restrict__ f3_w, const float* __restrict__ f3_b)
{
    int p = blockIdx.x * blockDim.x + threadIdx.x;
    if (p >= POSN) return;
    float bh = (float)(p / 31 - 15);
    float bw = (float)(p % 31 - 15);
    float a[8], y[8];
#pragma unroll
    for (int u = 0; u < 8; u++) a[u] = bh * pp_w[2 * u] + bw * pp_w[2 * u + 1] + pp_b[u];
    ln_relu8(a, l1_g, l1_b);
    fc8(a, y, f1_w, f1_b);
    ln_relu8(y, l2_g, l2_b);
    fc8(y, a, f2_w, f2_b);
    ln_relu8(a, l3_g, l3_b);
#pragma unroll
    for (int hh = 0; hh < HEADS; hh++) {
        float s = f3_b[hh];
#pragma unroll
        for (int u = 0; u < 8; u++) s += a[u] * f3_w[hh * 8 + u];
        g_pos[hh * POSN + p] = s;
    }
}

// ---------------- fold LN gamma into QKV weight + transpose ----------------
__global__ void prep_w_kernel(const float* __restrict__ qkv_w, const float* __restrict__ qkv_b,
                              const float* __restrict__ g1, const float* __restrict__ b1)
{
    __shared__ float s1[128], s2[128];
    int j = blockIdx.x;        // 0..383
    int k = threadIdx.x;       // 0..127
    float w = qkv_w[j * 128 + k];
    float wg = w * g1[k];
    g_wT[k * 384 + j] = wg;
    s1[k] = wg;
    s2[k] = w * b1[k];
    __syncthreads();
    for (int o = 64; o > 0; o >>= 1) {
        if (k < o) { s1[k] += s1[k + o]; s2[k] += s2[k + o]; }
        __syncthreads();
    }
    if (k == 0) { g_cs[j] = s1[0]; g_cb[j] = s2[0] + qkv_b[j]; }
}

// ---------------- fused LN + QKV GEMM (raw-x trick) ----------------
#define QK_PADA 132
#define QKV_SMEM_FLOATS (64 * QK_PADA + 64 * 384 + 64 + 64)

__global__ __launch_bounds__(256, 1) void qkv_kernel(const float* __restrict__ x)
{
    extern __shared__ float sm[];
    float* As    = sm;                         // [64][132] raw x tile
    float* Bs    = sm + 64 * QK_PADA;          // [64][384] weight k-tile
    float* smean = Bs + 64 * 384;              // [64]
    float* srstd = smean + 64;                 // [64]

    int tid = threadIdx.x;
    int t0 = blockIdx.x * 64;

    // load 64 token rows (gathered to window order) — coalesced float4
#pragma unroll
    for (int i = 0; i < 8; i++) {
        int f = i * 256 + tid;                 // 2048 float4
        int m = f >> 5, c4 = f & 31;
        int t = t0 + m;
        int w = t >> 8, n = t & 255;
        int row = ((w >> 8) << 16) + (((((w >> 4) & 15) << 4) + (n >> 4)) << 8)
                + ((w & 15) << 4) + (n & 15);
        *(float4*)(As + m * QK_PADA + c4 * 4) =
            *(const float4*)(x + (size_t)row * 128 + c4 * 4);
    }
    __syncthreads();

    // per-row LN stats (warp w handles rows w*8..w*8+7)
    {
        int wi = tid >> 5, lane = tid & 31;
        for (int rr = 0; rr < 8; rr++) {
            int m = wi * 8 + rr;
            float s = 0.f, q = 0.f;
#pragma unroll
            for (int c = 0; c < 4; c++) {
                float v = As[m * QK_PADA + lane + 32 * c];
                s += v; q += v * v;
            }
#pragma unroll
            for (int o = 16; o; o >>= 1) {
                s += __shfl_xor_sync(0xffffffffu, s, o);
                q += __shfl_xor_sync(0xffffffffu, q, o);
            }
            if (lane == 0) {
                float mu = s * (1.f / 128.f);
                smean[m] = mu;
                srstd[m] = rsqrtf(q * (1.f / 128.f) - mu * mu + 1e-5f);
            }
        }
    }

    int ty = tid >> 5, tx = tid & 31;
    float acc[8][12];
#pragma unroll
    for (int r = 0; r < 8; r++)
#pragma unroll
        for (int u = 0; u < 12; u++) acc[r][u] = 0.f;

    for (int kt = 0; kt < 2; kt++) {
        __syncthreads();
        // load B k-tile [64][384]
#pragma unroll
        for (int i = 0; i < 24; i++) {
            int f = i * 256 + tid;             // 6144 float4
            int kk = f / 96, c4 = f % 96;
            *(float4*)(Bs + kk * 384 + c4 * 4) =
                *(const float4*)(g_wT + (size_t)(kt * 64 + kk) * 384 + c4 * 4);
        }
        __syncthreads();
#pragma unroll 4
        for (int kk = 0; kk < 64; kk++) {
            float qa[8];
#pragma unroll
            for (int r = 0; r < 8; r++) qa[r] = As[(ty * 8 + r) * QK_PADA + kt * 64 + kk];
#pragma unroll
            for (int u = 0; u < 12; u++) {
                float bb = Bs[kk * 384 + tx + 32 * u];
#pragma unroll
                for (int r = 0; r < 8; r++) acc[r][u] += qa[r] * bb;
            }
        }
    }
    __syncthreads();

    // epilogue: apply LN analytically, scatter q/k/v window-partitioned
#pragma unroll
    for (int u = 0; u < 12; u++) {
        int j = tx + 32 * u;
        float cs = g_cs[j], cb = g_cb[j];
        int head = u & 3;
        float* dst = (u < 4) ? g_q : (u < 8) ? g_k : g_v;
#pragma unroll
        for (int r = 0; r < 8; r++) {
            int m = ty * 8 + r;
            int t = t0 + m;
            int w = t >> 8, n = t & 255;
            float val = srstd[m] * (acc[r][u] - smean[m] * cs) + cb;
            if (u < 4) val *= QKSCALE;
            dst[((size_t)(w * 4 + head) * 256 + n) * 32 + tx] = val;
        }
    }
}

// ---------------- attention: per (window, head) block ----------------
#define KSTRIDE 260
#define SSTRIDE 257
#define ATTN_SMEM_FLOATS (32*KSTRIDE + 32*KSTRIDE + 256*32 + 64*SSTRIDE + 964 + 256 + 256 + 64 + 64)

__global__ __launch_bounds__(256, 1) void attn_kernel(const float* __restrict__ x,
                                                      float* __restrict__ out)
{
    extern __shared__ float sm[];
    float* ks     = sm;                        // [32][260] k d-major
    float* qs     = ks + 32 * KSTRIDE;         // [32][260] q d-major (all 256 queries)
    float* vs     = qs + 32 * KSTRIDE;         // [256][32] v n-major
    float* Ss     = vs + 256 * 32;             // [64][257] scores / later partial-out
    float* posh   = Ss + 64 * SSTRIDE;         // [961] (+pad)
    float* pmax   = posh + 964;                // [4][64]
    float* psum   = pmax + 256;                // [4][64]
    float* rowmax = psum + 256;                // [64]
    float* rowsum = rowmax + 64;               // [64]

    int tid = threadIdx.x;
    int w = blockIdx.x >> 2, h = blockIdx.x & 3;
    size_t base = (size_t)(w * 4 + h) * 256 * 32;

    for (int p = tid; p < POSN; p += 256) posh[p] = g_pos[h * POSN + p];

    // load k,q (transpose to d-major) and v
#pragma unroll
    for (int i = 0; i < 8; i++) {
        int f = i * 256 + tid;                 // 2048 float4 each
        int n = f >> 3, d4 = f & 7;
        float4 kv = *(const float4*)(g_k + base + n * 32 + d4 * 4);
        ks[(d4 * 4 + 0) * KSTRIDE + n] = kv.x;
        ks[(d4 * 4 + 1) * KSTRIDE + n] = kv.y;
        ks[(d4 * 4 + 2) * KSTRIDE + n] = kv.z;
        ks[(d4 * 4 + 3) * KSTRIDE + n] = kv.w;
        float4 qv = *(const float4*)(g_q + base + n * 32 + d4 * 4);
        qs[(d4 * 4 + 0) * KSTRIDE + n] = qv.x;
        qs[(d4 * 4 + 1) * KSTRIDE + n] = qv.y;
        qs[(d4 * 4 + 2) * KSTRIDE + n] = qv.z;
        qs[(d4 * 4 + 3) * KSTRIDE + n] = qv.w;
        *(float4*)(vs + n * 32 + d4 * 4) = *(const float4*)(g_v + base + n * 32 + d4 * 4);
    }
    __syncthreads();

    int ty = tid >> 5, tx = tid & 31;
    int b  = w >> 8, wh = (w >> 4) & 15, ww = w & 15;

    for (int qt = 0; qt < 4; qt++) {
        int i0 = qt * 64;

        // ---- GEMM1: S = q @ k^T  (8 rows x 8 strided cols per thread) ----
        float acc[8][8];
#pragma unroll
        for (int r = 0; r < 8; r++)
#pragma unroll
            for (int u = 0; u < 8; u++) acc[r][u] = 0.f;

#pragma unroll 4
        for (int d = 0; d < 32; d++) {
            float qa[8], kb[8];
#pragma unroll
            for (int r = 0; r < 8; r++) qa[r] = qs[d * KSTRIDE + i0 + ty * 8 + r];
#pragma unroll
            for (int u = 0; u < 8; u++) kb[u] = ks[d * KSTRIDE + tx + 32 * u];
#pragma unroll
            for (int r = 0; r < 8; r++)
#pragma unroll
                for (int u = 0; u < 8; u++) acc[r][u] += qa[r] * kb[u];
        }

        // add rel-pos bias, store S (bank-conflict-free: j = tx + 32u)
#pragma unroll
        for (int r = 0; r < 8; r++) {
            int il = ty * 8 + r;
            int i  = i0 + il;
            int bi = ((i >> 4) + 15) * 31 + (i & 15) + 15;
#pragma unroll
            for (int u = 0; u < 8; u++) {
                int j = tx + 32 * u;
                int idx = bi - (j >> 4) * 31 - (j & 15);
                Ss[il * SSTRIDE + j] = acc[r][u] + posh[idx];
            }
        }
        __syncthreads();

        // ---- softmax (deferred 1/sum) ----
        int m = tid & 63, part = tid >> 6;
        {
            float mx = -1e30f;
#pragma unroll 8
            for (int jj = 0; jj < 64; jj++) mx = fmaxf(mx, Ss[m * SSTRIDE + part * 64 + jj]);
            pmax[part * 64 + m] = mx;
        }
        __syncthreads();
        if (tid < 64)
            rowmax[tid] = fmaxf(fmaxf(pmax[tid], pmax[64 + tid]),
                                fmaxf(pmax[128 + tid], pmax[192 + tid]));
        __syncthreads();
        {
            float mx = rowmax[m];
            float s = 0.f;
#pragma unroll 8
            for (int jj = 0; jj < 64; jj++) {
                float e = __expf(Ss[m * SSTRIDE + part * 64 + jj] - mx);
                Ss[m * SSTRIDE + part * 64 + jj] = e;
                s += e;
            }
            psum[part * 64 + m] = s;
        }
        __syncthreads();
        if (tid < 64)
            rowsum[tid] = psum[tid] + psum[64 + tid] + psum[128 + tid] + psum[192 + tid];
        __syncthreads();

        // ---- GEMM2: out = P @ v  (thread-per-row, 4-way k-split) ----
        float acc2[32];
#pragma unroll
        for (int d = 0; d < 32; d++) acc2[d] = 0.f;
#pragma unroll 4
        for (int kk = 0; kk < 64; kk++) {
            int k = part * 64 + kk;
            float pv = Ss[m * SSTRIDE + k];
#pragma unroll
            for (int d4 = 0; d4 < 8; d4++) {
                float4 vv = *(const float4*)(vs + k * 32 + d4 * 4);
                acc2[d4 * 4 + 0] += pv * vv.x;
                acc2[d4 * 4 + 1] += pv * vv.y;
                acc2[d4 * 4 + 2] += pv * vv.z;
                acc2[d4 * 4 + 3] += pv * vv.w;
            }
        }
        __syncthreads();            // all Ss reads complete; safe to alias as reduce buf

        float* red = Ss;            // [4][64][33]
#pragma unroll
        for (int d = 0; d < 32; d++) red[(part * 64 + m) * 33 + d] = acc2[d];
        __syncthreads();

        // finalize: combine k-splits, /rowsum, residual add, store
        if (tid < 64) {
            int mm = tid;
            int i  = i0 + mm;
            int row = (b << 16) + (((wh << 4) + (i >> 4)) << 8) + (ww << 4) + (i & 15);
            float inv = 1.f / rowsum[mm];
            const float* xr = x   + (size_t)row * 128 + h * 32;
            float*      orr = out + (size_t)row * 128 + h * 32;
#pragma unroll
            for (int d = 0; d < 32; d++) {
                float val = (red[mm * 33 + d] + red[(64 + mm) * 33 + d]
                           + red[(128 + mm) * 33 + d] + red[(192 + mm) * 33 + d]) * inv;
                orr[d] = xr[d] + val;
            }
        }
        __syncthreads();
    }
}

// ---------------- launch ----------------
extern "C" void kernel_launch(void* const* d_in, const int* in_sizes, int n_in,
                              void* d_out, int out_size)
{
    (void)in_sizes; (void)n_in; (void)out_size;
    const float* x      = (const float*)d_in[0];
    const float* n1g    = (const float*)d_in[1];
    const float* n1b    = (const float*)d_in[2];
    const float* qkv_w  = (const float*)d_in[3];
    const float* qkv_b  = (const float*)d_in[4];
    const float* pp_w   = (const float*)d_in[5];
    const float* pp_b   = (const float*)d_in[6];
    const float* l1_g   = (const float*)d_in[7];
    const float* l1_b   = (const float*)d_in[8];
    const float* f1_w   = (const float*)d_in[9];
    const float* f1_b   = (const float*)d_in[10];
    const float* l2_g   = (const float*)d_in[11];
    const float* l2_b   = (const float*)d_in[12];
    const float* f2_w   = (const float*)d_in[13];
    const float* f2_b   = (const float*)d_in[14];
    const float* l3_g   = (const float*)d_in[15];
    const float* l3_b   = (const float*)d_in[16];
    const float* f3_w   = (const float*)d_in[17];
    const float* f3_b   = (const float*)d_in[18];
    float* out = (float*)d_out;

    const int qkv_smem  = QKV_SMEM_FLOATS * 4;    // 132,608 B
    const int attn_smem = ATTN_SMEM_FLOATS * 4;   // 171,536 B
    cudaFuncSetAttribute(qkv_kernel,  cudaFuncAttributeMaxDynamicSharedMemorySize, qkv_smem);
    cudaFuncSetAttribute(attn_kernel, cudaFuncAttributeMaxDynamicSharedMemorySize, attn_smem);

    prep_pos_kernel<<<1, 1024>>>(pp_w, pp_b, l1_g, l1_b, f1_w, f1_b,
                                 l2_g, l2_b, f2_w, f2_b, l3_g, l3_b, f3_w, f3_b);
    prep_w_kernel<<<384, 128>>>(qkv_w, qkv_b, n1g, n1b);
    qkv_kernel<<<2048, 256, qkv_smem>>>(x);
    attn_kernel<<<2048, 256, attn_smem>>>(x, out);
}

// round 2
// speedup vs baseline: 1.3092x; 1.3092x over previous
#include <cuda_runtime.h>
#include <math.h>

#define HEADS   4
#define HD      32
#define NTOK    256
#define NWIN    512
#define POSN    961
#define QKSCALE 0.17677669529663689f  // 32^-0.5

// ---------------- scratch ----------------
__device__ float g_q[NWIN * HEADS * NTOK * HD];
__device__ float g_k[NWIN * HEADS * NTOK * HD];
__device__ float g_v[NWIN * HEADS * NTOK * HD];
__device__ float g_wT[128 * 384];
__device__ float g_cs[384];
__device__ float g_cb[384];
__device__ float g_pos[HEADS * POSN];

// ---------------- f32x2 helpers ----------------
typedef unsigned long long u64;
__device__ __forceinline__ u64 pk2(float x, float y) {
    u64 r; asm("mov.b64 %0,{%1,%2};" : "=l"(r) : "f"(x), "f"(y)); return r;
}
__device__ __forceinline__ void fma2(u64& d, u64 a, u64 b) {
    asm("fma.rn.f32x2 %0,%1,%2,%0;" : "+l"(d) : "l"(a), "l"(b));
}
__device__ __forceinline__ float2 up2(u64 v) {
    float lo, hi; asm("mov.b64 {%0,%1},%2;" : "=f"(lo), "=f"(hi) : "l"(v));
    float2 f; f.x = lo; f.y = hi; return f;
}

// ---------------- pos-bias MLP ----------------
__device__ __forceinline__ void ln_relu8(float* a, const float* g, const float* b) {
    float m = 0.f;
#pragma unroll
    for (int u = 0; u < 8; u++) m += a[u];
    m *= 0.125f;
    float v = 0.f;
#pragma unroll
    for (int u = 0; u < 8; u++) { float d = a[u] - m; v += d * d; }
    v *= 0.125f;
    float r = rsqrtf(v + 1e-5f);
#pragma unroll
    for (int u = 0; u < 8; u++) a[u] = fmaxf((a[u] - m) * r * g[u] + b[u], 0.f);
}

__device__ __forceinline__ void fc8(const float* a, float* y, const float* w, const float* b) {
#pragma unroll
    for (int o = 0; o < 8; o++) {
        float s = b[o];
#pragma unroll
        for (int u = 0; u < 8; u++) s += a[u] * w[o * 8 + u];
        y[o] = s;
    }
}

__global__ void prep_pos_kernel(
    const float* __restrict__ pp_w, const float* __restrict__ pp_b,
    const float* __restrict__ l1_g, const float* __restrict__ l1_b,
    const float* __restrict__ f1_w, const float* __restrict__ f1_b,
    const float* __restrict__ l2_g, const float* __restrict__ l2_b,
    const float* __restrict__ f2_w, const float* __restrict__ f2_b,
    const float* __restrict__ l3_g, const float* __restrict__ l3_b,
    const float* __restrict__ f3_w, const float* __restrict__ f3_b)
{
    int p = blockIdx.x * blockDim.x + threadIdx.x;
    if (p >= POSN) return;
    float bh = (float)(p / 31 - 15);
    float bw = (float)(p % 31 - 15);
    float a[8], y[8];
#pragma unroll
    for (int u = 0; u < 8; u++) a[u] = bh * pp_w[2 * u] + bw * pp_w[2 * u + 1] + pp_b[u];
    ln_relu8(a, l1_g, l1_b);
    fc8(a, y, f1_w, f1_b);
    ln_relu8(y, l2_g, l2_b);
    fc8(y, a, f2_w, f2_b);
    ln_relu8(a, l3_g, l3_b);
#pragma unroll
    for (int hh = 0; hh < HEADS; hh++) {
        float s = f3_b[hh];
#pragma unroll
        for (int u = 0; u < 8; u++) s += a[u] * f3_w[hh * 8 + u];
        g_pos[hh * POSN + p] = s;
    }
}

// ---------------- fold LN gamma into QKV weight ----------------
__global__ void prep_w_kernel(const float* __restrict__ qkv_w, const float* __restrict__ qkv_b,
                              const float* __restrict__ g1, const float* __restrict__ b1)
{
    __shared__ float s1[128], s2[128];
    int j = blockIdx.x;
    int k = threadIdx.x;
    float w = qkv_w[j * 128 + k];
    float wg = w * g1[k];
    g_wT[k * 384 + j] = wg;
    s1[k] = wg;
    s2[k] = w * b1[k];
    __syncthreads();
    for (int o = 64; o > 0; o >>= 1) {
        if (k < o) { s1[k] += s1[k + o]; s2[k] += s2[k + o]; }
        __syncthreads();
    }
    if (k == 0) { g_cs[j] = s1[0]; g_cb[j] = s2[0] + qkv_b[j]; }
}

// ---------------- fused LN + QKV GEMM (f32x2) ----------------
#define QK_PADA 132
#define QKV_SMEM_FLOATS (64 * QK_PADA + 64 * 384 + 64 + 64)

__global__ __launch_bounds__(256, 1) void qkv_kernel(const float* __restrict__ x)
{
    extern __shared__ float sm[];
    float* As    = sm;                         // [64][132]
    float* Bs    = sm + 64 * QK_PADA;          // [64][384]
    float* smean = Bs + 64 * 384;
    float* srstd = smean + 64;

    int tid = threadIdx.x;
    int t0 = blockIdx.x * 64;

#pragma unroll
    for (int i = 0; i < 8; i++) {
        int f = i * 256 + tid;
        int m = f >> 5, c4 = f & 31;
        int t = t0 + m;
        int w = t >> 8, n = t & 255;
        int row = ((w >> 8) << 16) + (((((w >> 4) & 15) << 4) + (n >> 4)) << 8)
                + ((w & 15) << 4) + (n & 15);
        *(float4*)(As + m * QK_PADA + c4 * 4) =
            *(const float4*)(x + (size_t)row * 128 + c4 * 4);
    }
    __syncthreads();

    {
        int wi = tid >> 5, lane = tid & 31;
        for (int rr = 0; rr < 8; rr++) {
            int m = wi * 8 + rr;
            float s = 0.f, q = 0.f;
#pragma unroll
            for (int c = 0; c < 4; c++) {
                float v = As[m * QK_PADA + lane + 32 * c];
                s += v; q += v * v;
            }
#pragma unroll
            for (int o = 16; o; o >>= 1) {
                s += __shfl_xor_sync(0xffffffffu, s, o);
                q += __shfl_xor_sync(0xffffffffu, q, o);
            }
            if (lane == 0) {
                float mu = s * (1.f / 128.f);
                smean[m] = mu;
                srstd[m] = rsqrtf(q * (1.f / 128.f) - mu * mu + 1e-5f);
            }
        }
    }

    int ty = tid >> 5, tx = tid & 31;
    u64 acc[4][12];
#pragma unroll
    for (int p = 0; p < 4; p++)
#pragma unroll
        for (int u = 0; u < 12; u++) acc[p][u] = 0ull;

    for (int kt = 0; kt < 2; kt++) {
        __syncthreads();
#pragma unroll
        for (int i = 0; i < 24; i++) {
            int f = i * 256 + tid;
            int kk = f / 96, c4 = f % 96;
            *(float4*)(Bs + kk * 384 + c4 * 4) =
                *(const float4*)(g_wT + (size_t)(kt * 64 + kk) * 384 + c4 * 4);
        }
        __syncthreads();
#pragma unroll 2
        for (int kk = 0; kk < 64; kk++) {
            const float* arow = As + (ty * 8) * QK_PADA + kt * 64 + kk;
            u64 qa[4];
#pragma unroll
            for (int p = 0; p < 4; p++)
                qa[p] = pk2(arow[(2 * p) * QK_PADA], arow[(2 * p + 1) * QK_PADA]);
            const float* brow = Bs + kk * 384 + tx;
#pragma unroll
            for (int u = 0; u < 12; u++) {
                float bb = brow[32 * u];
                u64 b2 = pk2(bb, bb);
#pragma unroll
                for (int p = 0; p < 4; p++) fma2(acc[p][u], qa[p], b2);
            }
        }
    }
    __syncthreads();

#pragma unroll
    for (int u = 0; u < 12; u++) {
        int j = tx + 32 * u;
        float cs = g_cs[j], cb = g_cb[j];
        int head = u & 3;
        float* dst = (u < 4) ? g_q : (u < 8) ? g_k : g_v;
#pragma unroll
        for (int p = 0; p < 4; p++) {
            float2 v = up2(acc[p][u]);
#pragma unroll
            for (int e = 0; e < 2; e++) {
                int m = ty * 8 + 2 * p + e;
                int t = t0 + m;
                int w = t >> 8, n = t & 255;
                float val = srstd[m] * (((e == 0) ? v.x : v.y) - smean[m] * cs) + cb;
                if (u < 4) val *= QKSCALE;
                dst[((size_t)(w * 4 + head) * 256 + n) * 32 + tx] = val;
            }
        }
    }
}

// ---------------- attention ----------------
#define KST 260
#define PST 66
#define RST 33
#define ATTN_SMEM_FLOATS (32*KST*2 + 256*32 + 256*PST + 256*RST + 964)

__global__ __launch_bounds__(256, 1) void attn_kernel(const float* __restrict__ x,
                                                      float* __restrict__ out)
{
    extern __shared__ float sm[];
    float* ks   = sm;                          // [32][260] k d-major
    float* qs   = ks + 32 * KST;               // [32][260] q d-major
    float* vs   = qs + 32 * KST;               // [256][32] v k-major
    float* Ps   = vs + 256 * 32;               // [256][66] P^T (k rows, m cols)
    float* red  = Ps + 256 * PST;              // [256][33] k-split partials
    float* posh = red + 256 * RST;             // [961]+pad

    int tid = threadIdx.x;
    int w = blockIdx.x >> 2, h = blockIdx.x & 3;
    size_t base = (size_t)(w * 4 + h) * 256 * 32;

    for (int p = tid; p < POSN; p += 256) posh[p] = g_pos[h * POSN + p];

    // v straight copy
#pragma unroll
    for (int i = 0; i < 8; i++) {
        int f = i * 256 + tid;
        int n = f >> 3, d4 = f & 7;
        *(float4*)(vs + n * 32 + d4 * 4) = *(const float4*)(g_v + base + n * 32 + d4 * 4);
    }

    // k,q transposed to d-major: warps 0-3 -> ks, warps 4-7 -> qs
    {
        int wi = tid >> 5, lx = tid & 31;
        const float* src = (wi < 4) ? (g_k + base) : (g_q + base);
        float* dst = (wi < 4) ? ks : qs;
        int w4 = wi & 3;
#pragma unroll
        for (int c = 0; c < 16; c++) {
            int n0 = w4 * 64 + c * 4;
            float t0 = src[(n0 + 0) * 32 + lx];
            float t1 = src[(n0 + 1) * 32 + lx];
            float t2 = src[(n0 + 2) * 32 + lx];
            float t3 = src[(n0 + 3) * 32 + lx];
            float4 val; val.x = t0; val.y = t1; val.z = t2; val.w = t3;
            *(float4*)(dst + lx * KST + n0) = val;
        }
    }
    __syncthreads();

    int ty = tid >> 5, tx = tid & 31;
    int b = w >> 8, wh = (w >> 4) & 15, ww = w & 15;

    for (int qt = 0; qt < 4; qt++) {
        int i0 = qt * 64;

        // ---- GEMM1: S = q @ k^T (f32x2, row-paired) ----
        u64 acc[4][8];
#pragma unroll
        for (int p = 0; p < 4; p++)
#pragma unroll
            for (int u = 0; u < 8; u++) acc[p][u] = 0ull;

#pragma unroll 4
        for (int d = 0; d < 32; d++) {
            const float* qrow = qs + d * KST + i0 + ty * 8;
            float4 ql = *(const float4*)qrow;
            float4 qh = *(const float4*)(qrow + 4);
            u64 qa[4];
            qa[0] = pk2(ql.x, ql.y); qa[1] = pk2(ql.z, ql.w);
            qa[2] = pk2(qh.x, qh.y); qa[3] = pk2(qh.z, qh.w);
            const float* krow = ks + d * KST + tx;
#pragma unroll
            for (int u = 0; u < 8; u++) {
                float kb = krow[32 * u];
                u64 b2 = pk2(kb, kb);
#pragma unroll
                for (int p = 0; p < 4; p++) fma2(acc[p][u], qa[p], b2);
            }
        }

        // ---- bias + warp-local softmax in registers ----
        float s[8][8];
#pragma unroll
        for (int p = 0; p < 4; p++)
#pragma unroll
            for (int u = 0; u < 8; u++) {
                float2 v = up2(acc[p][u]);
                s[2 * p][u] = v.x; s[2 * p + 1][u] = v.y;
            }
#pragma unroll
        for (int r = 0; r < 8; r++) {
            int i = i0 + ty * 8 + r;
            int bi = ((i >> 4) + 15) * 31 + (i & 15) + 15;
#pragma unroll
            for (int u = 0; u < 8; u++) {
                int j = tx + 32 * u;
                s[r][u] += posh[bi - (j >> 4) * 31 - (j & 15)];
            }
        }
#pragma unroll
        for (int r = 0; r < 8; r++) {
            float mx = s[r][0];
#pragma unroll
            for (int u = 1; u < 8; u++) mx = fmaxf(mx, s[r][u]);
#pragma unroll
            for (int o = 16; o; o >>= 1) mx = fmaxf(mx, __shfl_xor_sync(0xffffffffu, mx, o));
            float sum = 0.f;
#pragma unroll
            for (int u = 0; u < 8; u++) {
                float e = __expf(s[r][u] - mx);
                s[r][u] = e; sum += e;
            }
#pragma unroll
            for (int o = 16; o; o >>= 1) sum += __shfl_xor_sync(0xffffffffu, sum, o);
            float inv = __fdividef(1.f, sum);
#pragma unroll
            for (int u = 0; u < 8; u++) s[r][u] *= inv;   // pre-normalized P
        }
        // store P^T: Ps[j][m] (stride 66, conflict ~2-way)
#pragma unroll
        for (int u = 0; u < 8; u++) {
            int j = tx + 32 * u;
#pragma unroll
            for (int r = 0; r < 8; r++)
                Ps[j * PST + ty * 8 + r] = s[r][u];
        }
        __syncthreads();

        // ---- GEMM2: out = P @ v (f32x2, 4-way k-split) ----
        {
            int s4 = ty >> 1, hh = ty & 1;
            int mg = tx >> 3, dg = tx & 7;
            int m0 = hh * 32 + mg * 8;
            u64 a2[4][4];
#pragma unroll
            for (int p = 0; p < 4; p++)
#pragma unroll
                for (int c = 0; c < 4; c++) a2[p][c] = 0ull;

#pragma unroll 4
            for (int kk = 0; kk < 64; kk++) {
                int k = s4 * 64 + kk;
                const u64* prow = (const u64*)(Ps + k * PST + m0);
                u64 pa0 = prow[0], pa1 = prow[1], pa2 = prow[2], pa3 = prow[3];
                float4 vv = *(const float4*)(vs + k * 32 + dg * 4);
                u64 b0 = pk2(vv.x, vv.x), b1 = pk2(vv.y, vv.y),
                    b2 = pk2(vv.z, vv.z), b3 = pk2(vv.w, vv.w);
                fma2(a2[0][0], pa0, b0); fma2(a2[0][1], pa0, b1);
                fma2(a2[0][2], pa0, b2); fma2(a2[0][3], pa0, b3);
                fma2(a2[1][0], pa1, b0); fma2(a2[1][1], pa1, b1);
                fma2(a2[1][2], pa1, b2); fma2(a2[1][3], pa1, b3);
                fma2(a2[2][0], pa2, b0); fma2(a2[2][1], pa2, b1);
                fma2(a2[2][2], pa2, b2); fma2(a2[2][3], pa2, b3);
                fma2(a2[3][0], pa3, b0); fma2(a2[3][1], pa3, b1);
                fma2(a2[3][2], pa3, b2); fma2(a2[3][3], pa3, b3);
            }
#pragma unroll
            for (int p = 0; p < 4; p++)
#pragma unroll
                for (int c = 0; c < 4; c++) {
                    float2 v = up2(a2[p][c]);
                    red[(s4 * 64 + m0 + 2 * p) * RST + dg * 4 + c] = v.x;
                    red[(s4 * 64 + m0 + 2 * p + 1) * RST + dg * 4 + c] = v.y;
                }
        }
        __syncthreads();

        // ---- combine k-splits + residual + store ----
        {
            int m = tid & 63, dq = tid >> 6;
            int i = i0 + m;
            int row = (b << 16) + (((wh << 4) + (i >> 4)) << 8) + (ww << 4) + (i & 15);
            float o[8];
#pragma unroll
            for (int c = 0; c < 8; c++)
                o[c] = red[m * RST + dq * 8 + c] + red[(64 + m) * RST + dq * 8 + c]
                     + red[(128 + m) * RST + dq * 8 + c] + red[(192 + m) * RST + dq * 8 + c];
            const float* xr = x + (size_t)row * 128 + h * 32 + dq * 8;
            float* orr = out + (size_t)row * 128 + h * 32 + dq * 8;
            float4 x1 = *(const float4*)xr;
            float4 x2 = *(const float4*)(xr + 4);
            float4 o1; o1.x = o[0] + x1.x; o1.y = o[1] + x1.y; o1.z = o[2] + x1.z; o1.w = o[3] + x1.w;
            float4 o2; o2.x = o[4] + x2.x; o2.y = o[5] + x2.y; o2.z = o[6] + x2.z; o2.w = o[7] + x2.w;
            *(float4*)orr = o1;
            *(float4*)(orr + 4) = o2;
        }
        __syncthreads();
    }
}

// ---------------- launch ----------------
extern "C" void kernel_launch(void* const* d_in, const int* in_sizes, int n_in,
                              void* d_out, int out_size)
{
    (void)in_sizes; (void)n_in; (void)out_size;
    const float* x      = (const float*)d_in[0];
    const float* n1g    = (const float*)d_in[1];
    const float* n1b    = (const float*)d_in[2];
    const float* qkv_w  = (const float*)d_in[3];
    const float* qkv_b  = (const float*)d_in[4];
    const float* pp_w   = (const float*)d_in[5];
    const float* pp_b   = (const float*)d_in[6];
    const float* l1_g   = (const float*)d_in[7];
    const float* l1_b   = (const float*)d_in[8];
    const float* f1_w   = (const float*)d_in[9];
    const float* f1_b   = (const float*)d_in[10];
    const float* l2_g   = (const float*)d_in[11];
    const float* l2_b   = (const float*)d_in[12];
    const float* f2_w   = (const float*)d_in[13];
    const float* f2_b   = (const float*)d_in[14];
    const float* l3_g   = (const float*)d_in[15];
    const float* l3_b   = (const float*)d_in[16];
    const float* f3_w   = (const float*)d_in[17];
    const float* f3_b   = (const float*)d_in[18];
    float* out = (float*)d_out;

    const int qkv_smem  = QKV_SMEM_FLOATS * 4;
    const int attn_smem = ATTN_SMEM_FLOATS * 4;   // 204,560 B
    cudaFuncSetAttribute(qkv_kernel,  cudaFuncAttributeMaxDynamicSharedMemorySize, qkv_smem);
    cudaFuncSetAttribute(attn_kernel, cudaFuncAttributeMaxDynamicSharedMemorySize, attn_smem);

    prep_pos_kernel<<<1, 1024>>>(pp_w, pp_b, l1_g, l1_b, f1_w, f1_b,
                                 l2_g, l2_b, f2_w, f2_b, l3_g, l3_b, f3_w, f3_b);
    prep_w_kernel<<<384, 128>>>(qkv_w, qkv_b, n1g, n1b);
    qkv_kernel<<<2048, 256, qkv_smem>>>(x);
    attn_kernel<<<2048, 256, attn_smem>>>(x, out);
}